// round 9
// baseline (speedup 1.0000x reference)
#include <cuda_runtime.h>
#include <cuda_bf16.h>
#include <cstdint>
#include <math.h>

#define Bn 8
#define Cn 256
#define Nn 4096

#define L2E 1.4426950408889634f
#define C2  72.134752f        // 50 * log2(e)

// ---------------------------------------------------------------------------
// Scratch
// ---------------------------------------------------------------------------
__device__ __nv_bfloat16 g_qh[(size_t)Bn * Nn * Cn];   // q hi [B,N,C]
__device__ __nv_bfloat16 g_ql[(size_t)Bn * Nn * Cn];
__device__ __nv_bfloat16 g_kh[(size_t)Bn * Nn * Cn];   // k hi [B,N,C]
__device__ __nv_bfloat16 g_kl[(size_t)Bn * Nn * Cn];
__device__ __nv_bfloat16 g_vh[(size_t)Bn * Cn * Nn];   // v hi [B,C,N]
__device__ __nv_bfloat16 g_vl[(size_t)Bn * Cn * Nn];
__device__ float         g_S [(size_t)Bn * Nn * Nn];   // masked scores fp32
__device__ float         g_Z [(size_t)Bn * Nn];        // row sums -> reciprocals

// ---------------------------------------------------------------------------
// Helpers
// ---------------------------------------------------------------------------
__device__ __forceinline__ uint32_t smem_u32(const void* p) {
    uint32_t a;
    asm("{ .reg .u64 t; cvta.to.shared.u64 t, %1; cvt.u32.u64 %0, t; }"
        : "=r"(a) : "l"(p));
    return a;
}

#define SMEM_SWIZZLE_64B(off) ((off) ^ (((off) >> 3) & 0x30))

__device__ __forceinline__ void ldmx4(uint32_t* r, uint32_t a) {
    asm volatile("ldmatrix.sync.aligned.m8n8.x4.shared.b16 {%0,%1,%2,%3}, [%4];"
        : "=r"(r[0]), "=r"(r[1]), "=r"(r[2]), "=r"(r[3]) : "r"(a));
}

__device__ __forceinline__ void mma16816(float* d, const uint32_t* a,
                                         uint32_t b0, uint32_t b1) {
    asm volatile(
        "mma.sync.aligned.m16n8k16.row.col.f32.bf16.bf16.f32 "
        "{%0,%1,%2,%3}, {%4,%5,%6,%7}, {%8,%9}, {%0,%1,%2,%3};"
        : "+f"(d[0]), "+f"(d[1]), "+f"(d[2]), "+f"(d[3])
        : "r"(a[0]), "r"(a[1]), "r"(a[2]), "r"(a[3]), "r"(b0), "r"(b1));
}

__device__ __forceinline__ float ex2f(float x) {
    float y;
    asm("ex2.approx.f32 %0, %1;" : "=f"(y) : "f"(x));
    return y;
}

__device__ __forceinline__ void lds_f4(float4& v, uint32_t a) {
    asm volatile("ld.shared.v4.f32 {%0,%1,%2,%3}, [%4];"
        : "=f"(v.x), "=f"(v.y), "=f"(v.z), "=f"(v.w) : "r"(a));
}

__device__ __forceinline__ void sts_b32(uint32_t a, uint32_t v) {
    asm volatile("st.shared.b32 [%0], %1;" :: "r"(a), "r"(v) : "memory");
}

// bf16 hi pair; returns residuals
__device__ __forceinline__ uint32_t pack2(float a, float b, float& ra, float& rb) {
    __nv_bfloat16 ah = __float2bfloat16_rn(a);
    __nv_bfloat16 bh = __float2bfloat16_rn(b);
    ra = a - __bfloat162float(ah);
    rb = b - __bfloat162float(bh);
    __nv_bfloat162 t = __halves2bfloat162(ah, bh);
    return *reinterpret_cast<uint32_t*>(&t);
}

#define CP16(d, s) \
    asm volatile("cp.async.cg.shared.global [%0], [%1], 16;" :: "r"(d), "l"(s))
#define CP_COMMIT() asm volatile("cp.async.commit_group;" ::: "memory")
#define CP_WAIT3()  asm volatile("cp.async.wait_group 3;" ::: "memory")
#define CP_WAIT2()  asm volatile("cp.async.wait_group 2;" ::: "memory")
#define CP_WAIT1()  asm volatile("cp.async.wait_group 1;" ::: "memory")
#define CP_WAIT0()  asm volatile("cp.async.wait_group 0;" ::: "memory")

// ---------------------------------------------------------------------------
// Scores mainloop smem: 3 stages x 4 tiles (Ah,Al,Bh,Bl) x 8KB
// ---------------------------------------------------------------------------
#define TILE_B   8192
#define STAGE_B  (4 * TILE_B)
#define NSTAGES  3
#define MMA_SMEM (NSTAGES * STAGE_B)

// 128-row x 32-bf16 tile (64B rows, SW64), 256 threads
__device__ __forceinline__ void cp_tile(uint32_t sdst, const __nv_bfloat16* g,
                                        int rs, int tid) {
    #pragma unroll
    for (int t = 0; t < 2; t++) {
        int u = tid + t * 256;
        int row = u >> 2, q = u & 3;
        uint32_t d = sdst + SMEM_SWIZZLE_64B((uint32_t)(row * 64 + q * 16));
        CP16(d, g + (size_t)row * rs + q * 8);
    }
}

// ---------------------------------------------------------------------------
// Kernel 1: projection (SIMT fp32) -> bf16 hi/lo. vmode=0: [N,C]; 1: [C,N].
// ---------------------------------------------------------------------------
__device__ __forceinline__ void store8_bf16_split(__nv_bfloat16* dh,
                                                  __nv_bfloat16* dl,
                                                  const float* f) {
    uint4 uh, ul;
    __nv_bfloat162* ph = reinterpret_cast<__nv_bfloat162*>(&uh);
    __nv_bfloat162* pl = reinterpret_cast<__nv_bfloat162*>(&ul);
    #pragma unroll
    for (int k = 0; k < 4; k++) {
        float a = f[2 * k], b = f[2 * k + 1];
        __nv_bfloat16 ah = __float2bfloat16_rn(a);
        __nv_bfloat16 bh = __float2bfloat16_rn(b);
        float al = a - __bfloat162float(ah);
        float bl = b - __bfloat162float(bh);
        ph[k] = __halves2bfloat162(ah, bh);
        pl[k] = __halves2bfloat162(__float2bfloat16_rn(al), __float2bfloat16_rn(bl));
    }
    *reinterpret_cast<uint4*>(dh) = uh;
    *reinterpret_cast<uint4*>(dl) = ul;
}

__global__ void __launch_bounds__(256, 2)
proj_kernel(const float* __restrict__ x,
            const float* __restrict__ W,
            const float* __restrict__ bias,
            __nv_bfloat16* __restrict__ oh,
            __nv_bfloat16* __restrict__ ol,
            int vmode) {
    __shared__ __align__(16) float As[16][128];
    __shared__ __align__(16) float Bs[16][132];

    const int b  = blockIdx.z;
    const int o0 = blockIdx.y * 128;
    const int n0 = blockIdx.x * 128;
    const int tid = threadIdx.x;
    const int tx = tid & 15, ty = tid >> 4;

    const float* xb = x + (size_t)b * Cn * Nn;
    float acc[8][8] = {};

    for (int c0 = 0; c0 < Cn; c0 += 16) {
        #pragma unroll
        for (int k = 0; k < 2; k++) {
            int p = tid + k * 256;
            int cc = p >> 5, nn4 = (p & 31) * 4;
            *reinterpret_cast<float4*>(&As[cc][nn4]) =
                *reinterpret_cast<const float4*>(&xb[(size_t)(c0 + cc) * Nn + n0 + nn4]);
        }
        #pragma unroll
        for (int k = 0; k < 2; k++) {
            int p = tid + k * 256;
            int oo = p >> 2, c4 = (p & 3) * 4;
            float4 w = *reinterpret_cast<const float4*>(&W[(size_t)(o0 + oo) * Cn + c0 + c4]);
            Bs[c4 + 0][oo] = w.x;
            Bs[c4 + 1][oo] = w.y;
            Bs[c4 + 2][oo] = w.z;
            Bs[c4 + 3][oo] = w.w;
        }
        __syncthreads();

        #pragma unroll
        for (int cc = 0; cc < 16; cc++) {
            float4 a0 = *reinterpret_cast<const float4*>(&As[cc][ty * 8]);
            float4 a1 = *reinterpret_cast<const float4*>(&As[cc][ty * 8 + 4]);
            float4 b0 = *reinterpret_cast<const float4*>(&Bs[cc][tx * 8]);
            float4 b1 = *reinterpret_cast<const float4*>(&Bs[cc][tx * 8 + 4]);
            float a[8] = {a0.x, a0.y, a0.z, a0.w, a1.x, a1.y, a1.z, a1.w};
            float bb[8] = {b0.x, b0.y, b0.z, b0.w, b1.x, b1.y, b1.z, b1.w};
            #pragma unroll
            for (int i = 0; i < 8; i++)
                #pragma unroll
                for (int j = 0; j < 8; j++)
                    acc[i][j] += a[i] * bb[j];
        }
        __syncthreads();
    }

    float bj[8];
    #pragma unroll
    for (int j = 0; j < 8; j++) bj[j] = bias[o0 + tx * 8 + j];

    if (!vmode) {
        __nv_bfloat16* dh = oh + (size_t)b * Nn * Cn;
        __nv_bfloat16* dl = ol + (size_t)b * Nn * Cn;
        #pragma unroll
        for (int i = 0; i < 8; i++) {
            float f[8];
            #pragma unroll
            for (int j = 0; j < 8; j++) f[j] = acc[i][j] + bj[j];
            size_t base = (size_t)(n0 + ty * 8 + i) * Cn + o0 + tx * 8;
            store8_bf16_split(dh + base, dl + base, f);
        }
    } else {
        __nv_bfloat16* dh = oh + (size_t)b * Cn * Nn;
        __nv_bfloat16* dl = ol + (size_t)b * Cn * Nn;
        #pragma unroll
        for (int j = 0; j < 8; j++) {
            float f[8];
            #pragma unroll
            for (int i = 0; i < 8; i++) f[i] = acc[i][j] + bj[j];
            size_t base = (size_t)(o0 + tx * 8 + j) * Nn + n0 + ty * 8;
            store8_bf16_split(dh + base, dl + base, f);
        }
    }
}

// ---------------------------------------------------------------------------
// Kernel 2a/2c: zero / reciprocal for row sums
// ---------------------------------------------------------------------------
__global__ void zeroZ() { g_Z[(size_t)blockIdx.x * 256 + threadIdx.x] = 0.f; }
__global__ void recipZ() {
    size_t i = (size_t)blockIdx.x * 256 + threadIdx.x;
    g_Z[i] = 1.0f / g_Z[i];
}

// ---------------------------------------------------------------------------
// Kernel 2b: scores via HMMA + masked store + per-row exp partial sums.
// ---------------------------------------------------------------------------
__global__ void __launch_bounds__(256, 2)
scores_mma(const float* __restrict__ mask) {
    extern __shared__ char smem[];
    uint32_t sbase = smem_u32(smem);
    const int tid = threadIdx.x;
    const int wid = tid >> 5, lane = tid & 31;

    const int b  = blockIdx.z;
    const int i0 = blockIdx.y * 128;
    const int j0 = blockIdx.x * 128;

    const __nv_bfloat16* Ah = g_qh + ((size_t)b * Nn + i0) * Cn;
    const __nv_bfloat16* Al = g_ql + ((size_t)b * Nn + i0) * Cn;
    const __nv_bfloat16* Bh = g_kh + ((size_t)b * Nn + j0) * Cn;
    const __nv_bfloat16* Bl = g_kl + ((size_t)b * Nn + j0) * Cn;

    const int iBase = (wid >> 2) * 64;
    const int jBase = (wid & 3) * 32;
    const uint32_t lsw  = (uint32_t)(((lane >> 1) & 3) * 16);
    const uint32_t aoff = (uint32_t)((iBase + (lane & 15)) * 64 + (lane >> 4) * 16);
    const uint32_t boff = (uint32_t)((jBase + (lane & 15)) * 64 + (lane >> 4) * 16);

    float acc[4][4][4] = {};

    #pragma unroll
    for (int p = 0; p < 2; p++) {
        uint32_t st = sbase + p * STAGE_B;
        int ko = p * 32;
        cp_tile(st + 0 * TILE_B, Ah + ko, Cn, tid);
        cp_tile(st + 1 * TILE_B, Al + ko, Cn, tid);
        cp_tile(st + 2 * TILE_B, Bh + ko, Cn, tid);
        cp_tile(st + 3 * TILE_B, Bl + ko, Cn, tid);
        CP_COMMIT();
    }

    const int nch = Cn / 32;
    int stage = 0;
    #pragma unroll 1
    for (int c = 0; c < nch; c++) {
        if (c + 1 < nch) CP_WAIT1(); else CP_WAIT0();
        __syncthreads();

        if (c + 2 < nch) {
            int ps = stage + 2; if (ps >= NSTAGES) ps -= NSTAGES;
            uint32_t st = sbase + ps * STAGE_B;
            int ko = (c + 2) * 32;
            cp_tile(st + 0 * TILE_B, Ah + ko, Cn, tid);
            cp_tile(st + 1 * TILE_B, Al + ko, Cn, tid);
            cp_tile(st + 2 * TILE_B, Bh + ko, Cn, tid);
            cp_tile(st + 3 * TILE_B, Bl + ko, Cn, tid);
            CP_COMMIT();
        }

        uint32_t tb = sbase + stage * STAGE_B;
        #pragma unroll
        for (int ks = 0; ks < 2; ks++) {
            uint32_t kb = (uint32_t)(ks * 32);
            uint32_t ah[4][4], al[4][4];
            #pragma unroll
            for (int it = 0; it < 4; it++) {
                uint32_t o = (aoff + it * 1024 + kb) ^ lsw;
                ldmx4(ah[it], tb + o);
                ldmx4(al[it], tb + TILE_B + o);
            }
            uint32_t bh[4][2], bl[4][2];
            #pragma unroll
            for (int jp = 0; jp < 2; jp++) {
                uint32_t o = (boff + jp * 1024 + kb) ^ lsw;
                uint32_t t4[4];
                ldmx4(t4, tb + 2 * TILE_B + o);
                bh[jp * 2][0]     = t4[0]; bh[jp * 2][1]     = t4[2];
                bh[jp * 2 + 1][0] = t4[1]; bh[jp * 2 + 1][1] = t4[3];
                ldmx4(t4, tb + 3 * TILE_B + o);
                bl[jp * 2][0]     = t4[0]; bl[jp * 2][1]     = t4[2];
                bl[jp * 2 + 1][0] = t4[1]; bl[jp * 2 + 1][1] = t4[3];
            }
            #pragma unroll
            for (int it = 0; it < 4; it++)
                #pragma unroll
                for (int nt = 0; nt < 4; nt++)
                    mma16816(acc[it][nt], ah[it], bh[nt][0], bh[nt][1]);
            #pragma unroll
            for (int it = 0; it < 4; it++)
                #pragma unroll
                for (int nt = 0; nt < 4; nt++)
                    mma16816(acc[it][nt], ah[it], bl[nt][0], bl[nt][1]);
            #pragma unroll
            for (int it = 0; it < 4; it++)
                #pragma unroll
                for (int nt = 0; nt < 4; nt++)
                    mma16816(acc[it][nt], al[it], bh[nt][0], bh[nt][1]);
        }
        if (++stage == NSTAGES) stage = 0;
    }

    // Epilogue: masked store + exp partial row sums (offset C=50, base-2).
    const int g = lane >> 2, cp2 = (lane & 3) * 2;
    const float* mb = mask + (size_t)b * Nn;
    float* Sb = g_S + (size_t)b * Nn * Nn;
    float* Zb = g_Z + (size_t)b * Nn;

    #pragma unroll
    for (int it = 0; it < 4; it++) {
        int r1 = i0 + iBase + it * 16 + g;
        float m1 = mb[r1], m2 = mb[r1 + 8];
        float z1 = 0.f, z2 = 0.f;
        #pragma unroll
        for (int nt = 0; nt < 4; nt++) {
            int cc = j0 + jBase + nt * 8 + cp2;
            float2 v1 = {acc[it][nt][0] * m1, acc[it][nt][1] * m1};
            float2 v2 = {acc[it][nt][2] * m2, acc[it][nt][3] * m2};
            *reinterpret_cast<float2*>(&Sb[(size_t)r1 * Nn + cc])       = v1;
            *reinterpret_cast<float2*>(&Sb[(size_t)(r1 + 8) * Nn + cc]) = v2;
            z1 += ex2f(fmaf(v1.x, L2E, -C2)) + ex2f(fmaf(v1.y, L2E, -C2));
            z2 += ex2f(fmaf(v2.x, L2E, -C2)) + ex2f(fmaf(v2.y, L2E, -C2));
        }
        z1 += __shfl_xor_sync(0xffffffffu, z1, 1);
        z1 += __shfl_xor_sync(0xffffffffu, z1, 2);
        z2 += __shfl_xor_sync(0xffffffffu, z2, 1);
        z2 += __shfl_xor_sync(0xffffffffu, z2, 2);
        if ((lane & 3) == 0) {
            atomicAdd(&Zb[r1], z1);
            atomicAdd(&Zb[r1 + 8], z2);
        }
    }
}

// ---------------------------------------------------------------------------
// Kernel 3: fused normalize + PV + blend.
// CTA: q-tile 64 rows x full C=256. O^T[c][q] = sum_j V[c][j] * P[q][j].
// K-dim = j (4096) in 128 chunks of 32.
// Stage (40KB): Vh 16K | Vl 16K | rawS 8K.  4 stages + conv P (hi/lo 4K each).
// ---------------------------------------------------------------------------
#define PV_STAGE 40960
#define PV_VL    16384
#define PV_RAW   32768
#define PV_CONVH (4 * PV_STAGE)
#define PV_CONVL (PV_CONVH + 4096)
#define PV_SMEM  (PV_CONVL + 4096)

__global__ void __launch_bounds__(256)
pv_fused(const float* __restrict__ mask,
         const float* __restrict__ queries,
         float* __restrict__ out) {
    extern __shared__ char smem[];
    uint32_t sbase = smem_u32(smem);
    const int tid = threadIdx.x;
    const int wid = tid >> 5, lane = tid & 31;

    const int b  = blockIdx.z;
    const int q0 = blockIdx.x * 64;

    const __nv_bfloat16* Vh = g_vh + (size_t)b * Cn * Nn;
    const __nv_bfloat16* Vl = g_vl + (size_t)b * Cn * Nn;
    const float* Sb = g_S + (size_t)b * Nn * Nn + (size_t)q0 * Nn;

    // conversion mapping: thread -> col-quad cq, row base rb (rows rb, rb+32)
    const int cq = tid & 7, rb = tid >> 3;
    const float iz0 = g_Z[(size_t)b * Nn + q0 + rb];
    const float iz1 = g_Z[(size_t)b * Nn + q0 + rb + 32];

    // warp tiles: 64 c-rows x 32 q-cols; iBase over c, jBase over q
    const int iBase = (wid >> 1) * 64;
    const int jBase = (wid & 1) * 32;
    const uint32_t lsw  = (uint32_t)(((lane >> 1) & 3) * 16);
    const uint32_t aoff = (uint32_t)((iBase + (lane & 15)) * 64 + (lane >> 4) * 16);
    const uint32_t boff = (uint32_t)((jBase + (lane & 15)) * 64 + (lane >> 4) * 16);

    float acc[4][4][4] = {};

    // prefetch chunks 0..2
    #pragma unroll
    for (int p = 0; p < 3; p++) {
        uint32_t st = sbase + p * PV_STAGE;
        const __nv_bfloat16* vh = Vh + p * 32;
        const __nv_bfloat16* vl = Vl + p * 32;
        #pragma unroll
        for (int t = 0; t < 4; t++) {
            int u = tid + t * 256;
            int row = u >> 2, q = u & 3;
            uint32_t sw = SMEM_SWIZZLE_64B((uint32_t)(row * 64 + q * 16));
            CP16(st + sw, vh + (size_t)row * Nn + q * 8);
            CP16(st + PV_VL + sw, vl + (size_t)row * Nn + q * 8);
        }
        const float* sg = Sb + p * 32;
        #pragma unroll
        for (int t = 0; t < 2; t++) {
            int u = tid + t * 256;
            int row = u >> 3, q = u & 7;
            CP16(st + PV_RAW + (uint32_t)(row * 128 + q * 16),
                 sg + (size_t)row * Nn + q * 4);
        }
        CP_COMMIT();
    }

    const int nch = Nn / 32;   // 128
    #pragma unroll 1
    for (int c = 0; c < nch; c++) {
        __syncthreads();   // A: all warps done MMA(c-1) / convert(c-1)

        if (c + 3 < nch) {
            uint32_t st = sbase + ((c + 3) & 3) * PV_STAGE;
            const __nv_bfloat16* vh = Vh + (c + 3) * 32;
            const __nv_bfloat16* vl = Vl + (c + 3) * 32;
            #pragma unroll
            for (int t = 0; t < 4; t++) {
                int u = tid + t * 256;
                int row = u >> 2, q = u & 3;
                uint32_t sw = SMEM_SWIZZLE_64B((uint32_t)(row * 64 + q * 16));
                CP16(st + sw, vh + (size_t)row * Nn + q * 8);
                CP16(st + PV_VL + sw, vl + (size_t)row * Nn + q * 8);
            }
            const float* sg = Sb + (c + 3) * 32;
            #pragma unroll
            for (int t = 0; t < 2; t++) {
                int u = tid + t * 256;
                int row = u >> 3, q = u & 7;
                CP16(st + PV_RAW + (uint32_t)(row * 128 + q * 16),
                     sg + (size_t)row * Nn + q * 4);
            }
            CP_COMMIT();
            CP_WAIT3();
        } else if (c + 2 < nch) CP_WAIT2();
        else if (c + 1 < nch) CP_WAIT1();
        else CP_WAIT0();

        __syncthreads();   // B: chunk c data visible

        // convert raw S -> P bf16 hi/lo (normalized)
        {
            uint32_t rawb = sbase + (c & 3) * PV_STAGE + PV_RAW;
            #pragma unroll
            for (int i = 0; i < 2; i++) {
                int r = rb + i * 32;
                float4 s4;
                lds_f4(s4, rawb + (uint32_t)(r * 128 + cq * 16));
                float iz = i ? iz1 : iz0;
                float e0 = ex2f(fmaf(s4.x, L2E, -C2)) * iz;
                float e1 = ex2f(fmaf(s4.y, L2E, -C2)) * iz;
                float e2 = ex2f(fmaf(s4.z, L2E, -C2)) * iz;
                float e3 = ex2f(fmaf(s4.w, L2E, -C2)) * iz;
                float l0, l1, l2, l3;
                uint32_t h01 = pack2(e0, e1, l0, l1);
                uint32_t h23 = pack2(e2, e3, l2, l3);
                __nv_bfloat162 t01 = __halves2bfloat162(
                    __float2bfloat16_rn(l0), __float2bfloat16_rn(l1));
                __nv_bfloat162 t23 = __halves2bfloat162(
                    __float2bfloat16_rn(l2), __float2bfloat16_rn(l3));
                uint32_t sw = SMEM_SWIZZLE_64B((uint32_t)(r * 64 + cq * 8));
                sts_b32(sbase + PV_CONVH + sw,     h01);
                sts_b32(sbase + PV_CONVH + sw + 4, h23);
                sts_b32(sbase + PV_CONVL + sw,     *reinterpret_cast<uint32_t*>(&t01));
                sts_b32(sbase + PV_CONVL + sw + 4, *reinterpret_cast<uint32_t*>(&t23));
            }
        }
        __syncthreads();   // C: converted P visible

        uint32_t vb = sbase + (c & 3) * PV_STAGE;
        #pragma unroll
        for (int ks = 0; ks < 2; ks++) {
            uint32_t kb = (uint32_t)(ks * 32);
            uint32_t ah[4][4], al[4][4];
            #pragma unroll
            for (int it = 0; it < 4; it++) {
                uint32_t o = (aoff + it * 1024 + kb) ^ lsw;
                ldmx4(ah[it], vb + o);
                ldmx4(al[it], vb + PV_VL + o);
            }
            uint32_t bh[4][2], bl[4][2];
            #pragma unroll
            for (int jp = 0; jp < 2; jp++) {
                uint32_t o = (boff + jp * 1024 + kb) ^ lsw;
                uint32_t t4[4];
                ldmx4(t4, sbase + PV_CONVH + o);
                bh[jp * 2][0]     = t4[0]; bh[jp * 2][1]     = t4[2];
                bh[jp * 2 + 1][0] = t4[1]; bh[jp * 2 + 1][1] = t4[3];
                ldmx4(t4, sbase + PV_CONVL + o);
                bl[jp * 2][0]     = t4[0]; bl[jp * 2][1]     = t4[2];
                bl[jp * 2 + 1][0] = t4[1]; bl[jp * 2 + 1][1] = t4[3];
            }
            #pragma unroll
            for (int it = 0; it < 4; it++)
                #pragma unroll
                for (int nt = 0; nt < 4; nt++)
                    mma16816(acc[it][nt], ah[it], bh[nt][0], bh[nt][1]);
            #pragma unroll
            for (int it = 0; it < 4; it++)
                #pragma unroll
                for (int nt = 0; nt < 4; nt++)
                    mma16816(acc[it][nt], ah[it], bl[nt][0], bl[nt][1]);
            #pragma unroll
            for (int it = 0; it < 4; it++)
                #pragma unroll
                for (int nt = 0; nt < 4; nt++)
                    mma16816(acc[it][nt], al[it], bh[nt][0], bh[nt][1]);
        }
    }

    // Epilogue: out[b,c,q] = queries*m + (1-m)*attn  (rows=c, cols=q)
    const int g = lane >> 2, cp2 = (lane & 3) * 2;
    const float* mb = mask + (size_t)b * Nn;

    int   qc[4];
    float m0[4], m1[4];
    #pragma unroll
    for (int nt = 0; nt < 4; nt++) {
        qc[nt] = q0 + jBase + nt * 8 + cp2;
        m0[nt] = mb[qc[nt]];
        m1[nt] = mb[qc[nt] + 1];
    }

    #pragma unroll
    for (int it = 0; it < 4; it++) {
        int cr = iBase + it * 16 + g;
        #pragma unroll
        for (int nt = 0; nt < 4; nt++) {
            size_t gi1 = ((size_t)b * Cn + cr) * Nn + qc[nt];
            size_t gi2 = gi1 + (size_t)8 * Nn;
            float2 qa = *reinterpret_cast<const float2*>(&queries[gi1]);
            float2 qb = *reinterpret_cast<const float2*>(&queries[gi2]);
            float2 o1, o2;
            o1.x = qa.x * m0[nt] + (1.f - m0[nt]) * acc[it][nt][0];
            o1.y = qa.y * m1[nt] + (1.f - m1[nt]) * acc[it][nt][1];
            o2.x = qb.x * m0[nt] + (1.f - m0[nt]) * acc[it][nt][2];
            o2.y = qb.y * m1[nt] + (1.f - m1[nt]) * acc[it][nt][3];
            *reinterpret_cast<float2*>(&out[gi1]) = o1;
            *reinterpret_cast<float2*>(&out[gi2]) = o2;
        }
    }
}

// ---------------------------------------------------------------------------
// Launch
// ---------------------------------------------------------------------------
extern "C" void kernel_launch(void* const* d_in, const int* in_sizes, int n_in,
                              void* d_out, int out_size) {
    const float* queries = (const float*)d_in[0];
    const float* keys    = (const float*)d_in[1];
    const float* mask    = (const float*)d_in[2];
    const float* Wq      = (const float*)d_in[3];
    const float* bq      = (const float*)d_in[4];
    const float* Wk      = (const float*)d_in[5];
    const float* bk      = (const float*)d_in[6];
    const float* Wv      = (const float*)d_in[7];
    const float* bv      = (const float*)d_in[8];
    float* out = (float*)d_out;

    cudaFuncSetAttribute(scores_mma, cudaFuncAttributeMaxDynamicSharedMemorySize,
                         MMA_SMEM);
    cudaFuncSetAttribute(pv_fused, cudaFuncAttributeMaxDynamicSharedMemorySize,
                         PV_SMEM);

    __nv_bfloat16 *qh, *ql, *kh, *kl, *vh, *vl;
    cudaGetSymbolAddress((void**)&qh, g_qh);
    cudaGetSymbolAddress((void**)&ql, g_ql);
    cudaGetSymbolAddress((void**)&kh, g_kh);
    cudaGetSymbolAddress((void**)&kl, g_kl);
    cudaGetSymbolAddress((void**)&vh, g_vh);
    cudaGetSymbolAddress((void**)&vl, g_vl);

    dim3 gproj(Nn / 128, Cn / 128, Bn);
    proj_kernel<<<gproj, 256>>>(queries, Wq, bq, qh, ql, 0);
    proj_kernel<<<gproj, 256>>>(keys,    Wk, bk, kh, kl, 0);
    proj_kernel<<<gproj, 256>>>(keys,    Wv, bv, vh, vl, 1);

    zeroZ<<<(Bn * Nn) / 256, 256>>>();

    dim3 gsc(Nn / 128, Nn / 128, Bn);
    scores_mma<<<gsc, 256, MMA_SMEM>>>(mask);

    recipZ<<<(Bn * Nn) / 256, 256>>>();

    dim3 gpv(Nn / 64, 1, Bn);
    pv_fused<<<gpv, 256, PV_SMEM>>>(mask, queries, out);
}

// round 10
// speedup vs baseline: 1.1015x; 1.1015x over previous
#include <cuda_runtime.h>
#include <cuda_bf16.h>
#include <cstdint>
#include <math.h>

#define Bn 8
#define Cn 256
#define Nn 4096

#define L2E 1.4426950408889634f
#define C2  72.134752f        // 50 * log2(e)

// ---------------------------------------------------------------------------
// Scratch
// ---------------------------------------------------------------------------
__device__ __nv_bfloat16 g_qh[(size_t)Bn * Nn * Cn];   // q hi [B,N,C]
__device__ __nv_bfloat16 g_ql[(size_t)Bn * Nn * Cn];
__device__ __nv_bfloat16 g_kh[(size_t)Bn * Nn * Cn];   // k hi [B,N,C]
__device__ __nv_bfloat16 g_kl[(size_t)Bn * Nn * Cn];
__device__ __nv_bfloat16 g_vh[(size_t)Bn * Cn * Nn];   // v hi [B,C,N]
__device__ __nv_bfloat16 g_vl[(size_t)Bn * Cn * Nn];
__device__ float         g_S [(size_t)Bn * Nn * Nn];   // masked scores fp32
__device__ float         g_Z [(size_t)Bn * Nn];        // row exp sums

// ---------------------------------------------------------------------------
// Helpers
// ---------------------------------------------------------------------------
__device__ __forceinline__ uint32_t smem_u32(const void* p) {
    uint32_t a;
    asm("{ .reg .u64 t; cvta.to.shared.u64 t, %1; cvt.u32.u64 %0, t; }"
        : "=r"(a) : "l"(p));
    return a;
}

#define SMEM_SWIZZLE_64B(off) ((off) ^ (((off) >> 3) & 0x30))

__device__ __forceinline__ void ldmx4(uint32_t* r, uint32_t a) {
    asm volatile("ldmatrix.sync.aligned.m8n8.x4.shared.b16 {%0,%1,%2,%3}, [%4];"
        : "=r"(r[0]), "=r"(r[1]), "=r"(r[2]), "=r"(r[3]) : "r"(a));
}

__device__ __forceinline__ void mma16816(float* d, const uint32_t* a,
                                         uint32_t b0, uint32_t b1) {
    asm volatile(
        "mma.sync.aligned.m16n8k16.row.col.f32.bf16.bf16.f32 "
        "{%0,%1,%2,%3}, {%4,%5,%6,%7}, {%8,%9}, {%0,%1,%2,%3};"
        : "+f"(d[0]), "+f"(d[1]), "+f"(d[2]), "+f"(d[3])
        : "r"(a[0]), "r"(a[1]), "r"(a[2]), "r"(a[3]), "r"(b0), "r"(b1));
}

__device__ __forceinline__ float ex2f(float x) {
    float y;
    asm("ex2.approx.f32 %0, %1;" : "=f"(y) : "f"(x));
    return y;
}

__device__ __forceinline__ void lds_f4(float4& v, uint32_t a) {
    asm volatile("ld.shared.v4.f32 {%0,%1,%2,%3}, [%4];"
        : "=f"(v.x), "=f"(v.y), "=f"(v.z), "=f"(v.w) : "r"(a));
}

__device__ __forceinline__ void sts_b32(uint32_t a, uint32_t v) {
    asm volatile("st.shared.b32 [%0], %1;" :: "r"(a), "r"(v) : "memory");
}

__device__ __forceinline__ uint32_t pack2(float a, float b, float& ra, float& rb) {
    __nv_bfloat16 ah = __float2bfloat16_rn(a);
    __nv_bfloat16 bh = __float2bfloat16_rn(b);
    ra = a - __bfloat162float(ah);
    rb = b - __bfloat162float(bh);
    __nv_bfloat162 t = __halves2bfloat162(ah, bh);
    return *reinterpret_cast<uint32_t*>(&t);
}

#define CP16(d, s) \
    asm volatile("cp.async.cg.shared.global [%0], [%1], 16;" :: "r"(d), "l"(s))
#define CP_COMMIT() asm volatile("cp.async.commit_group;" ::: "memory")
#define CP_WAIT1()  asm volatile("cp.async.wait_group 1;" ::: "memory")
#define CP_WAIT0()  asm volatile("cp.async.wait_group 0;" ::: "memory")

// ---------------------------------------------------------------------------
// Scores mainloop smem: 3 stages x 4 tiles (Ah,Al,Bh,Bl) x 8KB
// ---------------------------------------------------------------------------
#define TILE_B   8192
#define STAGE_B  (4 * TILE_B)
#define NSTAGES  3
#define MMA_SMEM (NSTAGES * STAGE_B)

__device__ __forceinline__ void cp_tile(uint32_t sdst, const __nv_bfloat16* g,
                                        int rs, int tid) {
    #pragma unroll
    for (int t = 0; t < 2; t++) {
        int u = tid + t * 256;
        int row = u >> 2, q = u & 3;
        uint32_t d = sdst + SMEM_SWIZZLE_64B((uint32_t)(row * 64 + q * 16));
        CP16(d, g + (size_t)row * rs + q * 8);
    }
}

// ---------------------------------------------------------------------------
// Kernel 1: projection (SIMT fp32) -> bf16 hi/lo. vmode=0: [N,C]; 1: [C,N].
// ---------------------------------------------------------------------------
__device__ __forceinline__ void store8_bf16_split(__nv_bfloat16* dh,
                                                  __nv_bfloat16* dl,
                                                  const float* f) {
    uint4 uh, ul;
    __nv_bfloat162* ph = reinterpret_cast<__nv_bfloat162*>(&uh);
    __nv_bfloat162* pl = reinterpret_cast<__nv_bfloat162*>(&ul);
    #pragma unroll
    for (int k = 0; k < 4; k++) {
        float a = f[2 * k], b = f[2 * k + 1];
        __nv_bfloat16 ah = __float2bfloat16_rn(a);
        __nv_bfloat16 bh = __float2bfloat16_rn(b);
        float al = a - __bfloat162float(ah);
        float bl = b - __bfloat162float(bh);
        ph[k] = __halves2bfloat162(ah, bh);
        pl[k] = __halves2bfloat162(__float2bfloat16_rn(al), __float2bfloat16_rn(bl));
    }
    *reinterpret_cast<uint4*>(dh) = uh;
    *reinterpret_cast<uint4*>(dl) = ul;
}

__global__ void __launch_bounds__(256, 2)
proj_kernel(const float* __restrict__ x,
            const float* __restrict__ W,
            const float* __restrict__ bias,
            __nv_bfloat16* __restrict__ oh,
            __nv_bfloat16* __restrict__ ol,
            int vmode) {
    __shared__ __align__(16) float As[16][128];
    __shared__ __align__(16) float Bs[16][132];

    const int b  = blockIdx.z;
    const int o0 = blockIdx.y * 128;
    const int n0 = blockIdx.x * 128;
    const int tid = threadIdx.x;
    const int tx = tid & 15, ty = tid >> 4;

    const float* xb = x + (size_t)b * Cn * Nn;
    float acc[8][8] = {};

    for (int c0 = 0; c0 < Cn; c0 += 16) {
        #pragma unroll
        for (int k = 0; k < 2; k++) {
            int p = tid + k * 256;
            int cc = p >> 5, nn4 = (p & 31) * 4;
            *reinterpret_cast<float4*>(&As[cc][nn4]) =
                *reinterpret_cast<const float4*>(&xb[(size_t)(c0 + cc) * Nn + n0 + nn4]);
        }
        #pragma unroll
        for (int k = 0; k < 2; k++) {
            int p = tid + k * 256;
            int oo = p >> 2, c4 = (p & 3) * 4;
            float4 w = *reinterpret_cast<const float4*>(&W[(size_t)(o0 + oo) * Cn + c0 + c4]);
            Bs[c4 + 0][oo] = w.x;
            Bs[c4 + 1][oo] = w.y;
            Bs[c4 + 2][oo] = w.z;
            Bs[c4 + 3][oo] = w.w;
        }
        __syncthreads();

        #pragma unroll
        for (int cc = 0; cc < 16; cc++) {
            float4 a0 = *reinterpret_cast<const float4*>(&As[cc][ty * 8]);
            float4 a1 = *reinterpret_cast<const float4*>(&As[cc][ty * 8 + 4]);
            float4 b0 = *reinterpret_cast<const float4*>(&Bs[cc][tx * 8]);
            float4 b1 = *reinterpret_cast<const float4*>(&Bs[cc][tx * 8 + 4]);
            float a[8] = {a0.x, a0.y, a0.z, a0.w, a1.x, a1.y, a1.z, a1.w};
            float bb[8] = {b0.x, b0.y, b0.z, b0.w, b1.x, b1.y, b1.z, b1.w};
            #pragma unroll
            for (int i = 0; i < 8; i++)
                #pragma unroll
                for (int j = 0; j < 8; j++)
                    acc[i][j] += a[i] * bb[j];
        }
        __syncthreads();
    }

    float bj[8];
    #pragma unroll
    for (int j = 0; j < 8; j++) bj[j] = bias[o0 + tx * 8 + j];

    if (!vmode) {
        __nv_bfloat16* dh = oh + (size_t)b * Nn * Cn;
        __nv_bfloat16* dl = ol + (size_t)b * Nn * Cn;
        #pragma unroll
        for (int i = 0; i < 8; i++) {
            float f[8];
            #pragma unroll
            for (int j = 0; j < 8; j++) f[j] = acc[i][j] + bj[j];
            size_t base = (size_t)(n0 + ty * 8 + i) * Cn + o0 + tx * 8;
            store8_bf16_split(dh + base, dl + base, f);
        }
    } else {
        __nv_bfloat16* dh = oh + (size_t)b * Cn * Nn;
        __nv_bfloat16* dl = ol + (size_t)b * Cn * Nn;
        #pragma unroll
        for (int j = 0; j < 8; j++) {
            float f[8];
            #pragma unroll
            for (int i = 0; i < 8; i++) f[i] = acc[i][j] + bj[j];
            size_t base = (size_t)(o0 + tx * 8 + j) * Nn + n0 + ty * 8;
            store8_bf16_split(dh + base, dl + base, f);
        }
    }
}

// ---------------------------------------------------------------------------
// Kernel 2a: zero row sums
// ---------------------------------------------------------------------------
__global__ void zeroZ() { g_Z[(size_t)blockIdx.x * 256 + threadIdx.x] = 0.f; }

// ---------------------------------------------------------------------------
// Kernel 2b: scores via HMMA + masked store + per-row exp partial sums.
// ---------------------------------------------------------------------------
__global__ void __launch_bounds__(256, 2)
scores_mma(const float* __restrict__ mask) {
    extern __shared__ char smem[];
    uint32_t sbase = smem_u32(smem);
    const int tid = threadIdx.x;
    const int wid = tid >> 5, lane = tid & 31;

    const int b  = blockIdx.z;
    const int i0 = blockIdx.y * 128;
    const int j0 = blockIdx.x * 128;

    const __nv_bfloat16* Ah = g_qh + ((size_t)b * Nn + i0) * Cn;
    const __nv_bfloat16* Al = g_ql + ((size_t)b * Nn + i0) * Cn;
    const __nv_bfloat16* Bh = g_kh + ((size_t)b * Nn + j0) * Cn;
    const __nv_bfloat16* Bl = g_kl + ((size_t)b * Nn + j0) * Cn;

    const int iBase = (wid >> 2) * 64;
    const int jBase = (wid & 3) * 32;
    const uint32_t lsw  = (uint32_t)(((lane >> 1) & 3) * 16);
    const uint32_t aoff = (uint32_t)((iBase + (lane & 15)) * 64 + (lane >> 4) * 16);
    const uint32_t boff = (uint32_t)((jBase + (lane & 15)) * 64 + (lane >> 4) * 16);

    float acc[4][4][4] = {};

    #pragma unroll
    for (int p = 0; p < 2; p++) {
        uint32_t st = sbase + p * STAGE_B;
        int ko = p * 32;
        cp_tile(st + 0 * TILE_B, Ah + ko, Cn, tid);
        cp_tile(st + 1 * TILE_B, Al + ko, Cn, tid);
        cp_tile(st + 2 * TILE_B, Bh + ko, Cn, tid);
        cp_tile(st + 3 * TILE_B, Bl + ko, Cn, tid);
        CP_COMMIT();
    }

    const int nch = Cn / 32;
    int stage = 0;
    #pragma unroll 1
    for (int c = 0; c < nch; c++) {
        if (c + 1 < nch) CP_WAIT1(); else CP_WAIT0();
        __syncthreads();

        if (c + 2 < nch) {
            int ps = stage + 2; if (ps >= NSTAGES) ps -= NSTAGES;
            uint32_t st = sbase + ps * STAGE_B;
            int ko = (c + 2) * 32;
            cp_tile(st + 0 * TILE_B, Ah + ko, Cn, tid);
            cp_tile(st + 1 * TILE_B, Al + ko, Cn, tid);
            cp_tile(st + 2 * TILE_B, Bh + ko, Cn, tid);
            cp_tile(st + 3 * TILE_B, Bl + ko, Cn, tid);
            CP_COMMIT();
        }

        uint32_t tb = sbase + stage * STAGE_B;
        #pragma unroll
        for (int ks = 0; ks < 2; ks++) {
            uint32_t kb = (uint32_t)(ks * 32);
            uint32_t ah[4][4], al[4][4];
            #pragma unroll
            for (int it = 0; it < 4; it++) {
                uint32_t o = (aoff + it * 1024 + kb) ^ lsw;
                ldmx4(ah[it], tb + o);
                ldmx4(al[it], tb + TILE_B + o);
            }
            uint32_t bh[4][2], bl[4][2];
            #pragma unroll
            for (int jp = 0; jp < 2; jp++) {
                uint32_t o = (boff + jp * 1024 + kb) ^ lsw;
                uint32_t t4[4];
                ldmx4(t4, tb + 2 * TILE_B + o);
                bh[jp * 2][0]     = t4[0]; bh[jp * 2][1]     = t4[2];
                bh[jp * 2 + 1][0] = t4[1]; bh[jp * 2 + 1][1] = t4[3];
                ldmx4(t4, tb + 3 * TILE_B + o);
                bl[jp * 2][0]     = t4[0]; bl[jp * 2][1]     = t4[2];
                bl[jp * 2 + 1][0] = t4[1]; bl[jp * 2 + 1][1] = t4[3];
            }
            #pragma unroll
            for (int it = 0; it < 4; it++)
                #pragma unroll
                for (int nt = 0; nt < 4; nt++)
                    mma16816(acc[it][nt], ah[it], bh[nt][0], bh[nt][1]);
            #pragma unroll
            for (int it = 0; it < 4; it++)
                #pragma unroll
                for (int nt = 0; nt < 4; nt++)
                    mma16816(acc[it][nt], ah[it], bl[nt][0], bl[nt][1]);
            #pragma unroll
            for (int it = 0; it < 4; it++)
                #pragma unroll
                for (int nt = 0; nt < 4; nt++)
                    mma16816(acc[it][nt], al[it], bh[nt][0], bh[nt][1]);
        }
        if (++stage == NSTAGES) stage = 0;
    }

    // Epilogue: masked store + exp partial row sums (offset 50, base-2).
    const int g = lane >> 2, cp2 = (lane & 3) * 2;
    const float* mb = mask + (size_t)b * Nn;
    float* Sb = g_S + (size_t)b * Nn * Nn;
    float* Zb = g_Z + (size_t)b * Nn;

    #pragma unroll
    for (int it = 0; it < 4; it++) {
        int r1 = i0 + iBase + it * 16 + g;
        float m1 = mb[r1], m2 = mb[r1 + 8];
        float z1 = 0.f, z2 = 0.f;
        #pragma unroll
        for (int nt = 0; nt < 4; nt++) {
            int cc = j0 + jBase + nt * 8 + cp2;
            float2 v1 = {acc[it][nt][0] * m1, acc[it][nt][1] * m1};
            float2 v2 = {acc[it][nt][2] * m2, acc[it][nt][3] * m2};
            *reinterpret_cast<float2*>(&Sb[(size_t)r1 * Nn + cc])       = v1;
            *reinterpret_cast<float2*>(&Sb[(size_t)(r1 + 8) * Nn + cc]) = v2;
            z1 += ex2f(fmaf(v1.x, L2E, -C2)) + ex2f(fmaf(v1.y, L2E, -C2));
            z2 += ex2f(fmaf(v2.x, L2E, -C2)) + ex2f(fmaf(v2.y, L2E, -C2));
        }
        z1 += __shfl_xor_sync(0xffffffffu, z1, 1);
        z1 += __shfl_xor_sync(0xffffffffu, z1, 2);
        z2 += __shfl_xor_sync(0xffffffffu, z2, 1);
        z2 += __shfl_xor_sync(0xffffffffu, z2, 2);
        if ((lane & 3) == 0) {
            atomicAdd(&Zb[r1], z1);
            atomicAdd(&Zb[r1 + 8], z2);
        }
    }
}

// ---------------------------------------------------------------------------
// Kernel 3: fused normalize + PV + blend.
// CTA: q-tile 64 x full C=256.  O^T[c][q] = sum_j V[c][j] * P[q][j].
// 2 stages x 40KB (Vh 16K | Vl 16K | rawS 8K) + 2 conv bufs (8K each) = 96KB
// -> 2 CTAs/SM.  2 barriers/chunk:
//   wait0 -> sync -> prefetch(c+1) -> convert(c) -> sync -> MMA(c)
// ---------------------------------------------------------------------------
#define PV_STAGE 40960
#define PV_VL    16384
#define PV_RAW   32768
#define PV_CONVB 81920                 // conv buffer s at PV_CONVB + s*8192 (hi), +4096 (lo)
#define PV_SMEM  (PV_CONVB + 2 * 8192)

__device__ __forceinline__ void pv_prefetch(uint32_t st,
                                            const __nv_bfloat16* vh,
                                            const __nv_bfloat16* vl,
                                            const float* sg, int tid) {
    #pragma unroll
    for (int t = 0; t < 4; t++) {
        int u = tid + t * 256;
        int row = u >> 2, q = u & 3;
        uint32_t sw = SMEM_SWIZZLE_64B((uint32_t)(row * 64 + q * 16));
        CP16(st + sw, vh + (size_t)row * Nn + q * 8);
        CP16(st + PV_VL + sw, vl + (size_t)row * Nn + q * 8);
    }
    #pragma unroll
    for (int t = 0; t < 2; t++) {
        int u = tid + t * 256;
        int row = u >> 3, q = u & 7;
        CP16(st + PV_RAW + (uint32_t)(row * 128 + q * 16),
             sg + (size_t)row * Nn + q * 4);
    }
    CP_COMMIT();
}

__global__ void __launch_bounds__(256, 2)
pv_fused(const float* __restrict__ mask,
         const float* __restrict__ queries,
         float* __restrict__ out) {
    extern __shared__ char smem[];
    uint32_t sbase = smem_u32(smem);
    const int tid = threadIdx.x;
    const int wid = tid >> 5, lane = tid & 31;

    const int b  = blockIdx.z;
    const int q0 = blockIdx.x * 64;

    const __nv_bfloat16* Vh = g_vh + (size_t)b * Cn * Nn;
    const __nv_bfloat16* Vl = g_vl + (size_t)b * Cn * Nn;
    const float* Sb = g_S + (size_t)b * Nn * Nn + (size_t)q0 * Nn;

    // conversion mapping: col-quad cq, row base rb (rows rb, rb+32)
    const int cq = tid & 7, rb = tid >> 3;
    const float iz0 = 1.0f / g_Z[(size_t)b * Nn + q0 + rb];
    const float iz1 = 1.0f / g_Z[(size_t)b * Nn + q0 + rb + 32];

    // warp tiles: 64 c-rows x 32 q-cols
    const int iBase = (wid >> 1) * 64;
    const int jBase = (wid & 1) * 32;
    const uint32_t lsw  = (uint32_t)(((lane >> 1) & 3) * 16);
    const uint32_t aoff = (uint32_t)((iBase + (lane & 15)) * 64 + (lane >> 4) * 16);
    const uint32_t boff = (uint32_t)((jBase + (lane & 15)) * 64 + (lane >> 4) * 16);

    float acc[4][4][4] = {};

    pv_prefetch(sbase, Vh, Vl, Sb, tid);

    const int nch = Nn / 32;   // 128
    #pragma unroll 1
    for (int c = 0; c < nch; c++) {
        CP_WAIT0();
        __syncthreads();   // chunk c visible; all warps done with chunk c-1

        if (c + 1 < nch)
            pv_prefetch(sbase + ((c + 1) & 1) * PV_STAGE,
                        Vh + (c + 1) * 32, Vl + (c + 1) * 32,
                        Sb + (c + 1) * 32, tid);

        // convert raw S(c) -> normalized P bf16 hi/lo
        {
            uint32_t rawb = sbase + (c & 1) * PV_STAGE + PV_RAW;
            uint32_t cvh  = sbase + PV_CONVB + (c & 1) * 8192;
            #pragma unroll
            for (int i = 0; i < 2; i++) {
                int r = rb + i * 32;
                float4 s4;
                lds_f4(s4, rawb + (uint32_t)(r * 128 + cq * 16));
                float iz = i ? iz1 : iz0;
                float e0 = ex2f(fmaf(s4.x, L2E, -C2)) * iz;
                float e1 = ex2f(fmaf(s4.y, L2E, -C2)) * iz;
                float e2 = ex2f(fmaf(s4.z, L2E, -C2)) * iz;
                float e3 = ex2f(fmaf(s4.w, L2E, -C2)) * iz;
                float l0, l1, l2, l3;
                uint32_t h01 = pack2(e0, e1, l0, l1);
                uint32_t h23 = pack2(e2, e3, l2, l3);
                __nv_bfloat162 t01 = __halves2bfloat162(
                    __float2bfloat16_rn(l0), __float2bfloat16_rn(l1));
                __nv_bfloat162 t23 = __halves2bfloat162(
                    __float2bfloat16_rn(l2), __float2bfloat16_rn(l3));
                uint32_t sw = SMEM_SWIZZLE_64B((uint32_t)(r * 64 + cq * 8));
                sts_b32(cvh + sw,            h01);
                sts_b32(cvh + sw + 4,        h23);
                sts_b32(cvh + 4096 + sw,     *reinterpret_cast<uint32_t*>(&t01));
                sts_b32(cvh + 4096 + sw + 4, *reinterpret_cast<uint32_t*>(&t23));
            }
        }
        __syncthreads();   // converted P visible

        uint32_t vb  = sbase + (c & 1) * PV_STAGE;
        uint32_t cvh = sbase + PV_CONVB + (c & 1) * 8192;
        #pragma unroll
        for (int ks = 0; ks < 2; ks++) {
            uint32_t kb = (uint32_t)(ks * 32);
            uint32_t ah[4][4], al[4][4];
            #pragma unroll
            for (int it = 0; it < 4; it++) {
                uint32_t o = (aoff + it * 1024 + kb) ^ lsw;
                ldmx4(ah[it], vb + o);
                ldmx4(al[it], vb + PV_VL + o);
            }
            uint32_t bh[4][2], bl[4][2];
            #pragma unroll
            for (int jp = 0; jp < 2; jp++) {
                uint32_t o = (boff + jp * 1024 + kb) ^ lsw;
                uint32_t t4[4];
                ldmx4(t4, cvh + o);
                bh[jp * 2][0]     = t4[0]; bh[jp * 2][1]     = t4[2];
                bh[jp * 2 + 1][0] = t4[1]; bh[jp * 2 + 1][1] = t4[3];
                ldmx4(t4, cvh + 4096 + o);
                bl[jp * 2][0]     = t4[0]; bl[jp * 2][1]     = t4[2];
                bl[jp * 2 + 1][0] = t4[1]; bl[jp * 2 + 1][1] = t4[3];
            }
            #pragma unroll
            for (int it = 0; it < 4; it++)
                #pragma unroll
                for (int nt = 0; nt < 4; nt++)
                    mma16816(acc[it][nt], ah[it], bh[nt][0], bh[nt][1]);
            #pragma unroll
            for (int it = 0; it < 4; it++)
                #pragma unroll
                for (int nt = 0; nt < 4; nt++)
                    mma16816(acc[it][nt], ah[it], bl[nt][0], bl[nt][1]);
            #pragma unroll
            for (int it = 0; it < 4; it++)
                #pragma unroll
                for (int nt = 0; nt < 4; nt++)
                    mma16816(acc[it][nt], al[it], bh[nt][0], bh[nt][1]);
        }
    }

    // Epilogue: out[b,c,q] = queries*m + (1-m)*attn  (rows=c, cols=q)
    const int g = lane >> 2, cp2 = (lane & 3) * 2;
    const float* mb = mask + (size_t)b * Nn;

    int   qc[4];
    float m0[4], m1[4];
    #pragma unroll
    for (int nt = 0; nt < 4; nt++) {
        qc[nt] = q0 + jBase + nt * 8 + cp2;
        m0[nt] = mb[qc[nt]];
        m1[nt] = mb[qc[nt] + 1];
    }

    #pragma unroll
    for (int it = 0; it < 4; it++) {
        int cr = iBase + it * 16 + g;
        #pragma unroll
        for (int nt = 0; nt < 4; nt++) {
            size_t gi1 = ((size_t)b * Cn + cr) * Nn + qc[nt];
            size_t gi2 = gi1 + (size_t)8 * Nn;
            float2 qa = *reinterpret_cast<const float2*>(&queries[gi1]);
            float2 qb = *reinterpret_cast<const float2*>(&queries[gi2]);
            float2 o1, o2;
            o1.x = qa.x * m0[nt] + (1.f - m0[nt]) * acc[it][nt][0];
            o1.y = qa.y * m1[nt] + (1.f - m1[nt]) * acc[it][nt][1];
            o2.x = qb.x * m0[nt] + (1.f - m0[nt]) * acc[it][nt][2];
            o2.y = qb.y * m1[nt] + (1.f - m1[nt]) * acc[it][nt][3];
            *reinterpret_cast<float2*>(&out[gi1]) = o1;
            *reinterpret_cast<float2*>(&out[gi2]) = o2;
        }
    }
}

// ---------------------------------------------------------------------------
// Launch
// ---------------------------------------------------------------------------
extern "C" void kernel_launch(void* const* d_in, const int* in_sizes, int n_in,
                              void* d_out, int out_size) {
    const float* queries = (const float*)d_in[0];
    const float* keys    = (const float*)d_in[1];
    const float* mask    = (const float*)d_in[2];
    const float* Wq      = (const float*)d_in[3];
    const float* bq      = (const float*)d_in[4];
    const float* Wk      = (const float*)d_in[5];
    const float* bk      = (const float*)d_in[6];
    const float* Wv      = (const float*)d_in[7];
    const float* bv      = (const float*)d_in[8];
    float* out = (float*)d_out;

    cudaFuncSetAttribute(scores_mma, cudaFuncAttributeMaxDynamicSharedMemorySize,
                         MMA_SMEM);
    cudaFuncSetAttribute(pv_fused, cudaFuncAttributeMaxDynamicSharedMemorySize,
                         PV_SMEM);

    __nv_bfloat16 *qh, *ql, *kh, *kl, *vh, *vl;
    cudaGetSymbolAddress((void**)&qh, g_qh);
    cudaGetSymbolAddress((void**)&ql, g_ql);
    cudaGetSymbolAddress((void**)&kh, g_kh);
    cudaGetSymbolAddress((void**)&kl, g_kl);
    cudaGetSymbolAddress((void**)&vh, g_vh);
    cudaGetSymbolAddress((void**)&vl, g_vl);

    dim3 gproj(Nn / 128, Cn / 128, Bn);
    proj_kernel<<<gproj, 256>>>(queries, Wq, bq, qh, ql, 0);
    proj_kernel<<<gproj, 256>>>(keys,    Wk, bk, kh, kl, 0);
    proj_kernel<<<gproj, 256>>>(keys,    Wv, bv, vh, vl, 1);

    zeroZ<<<(Bn * Nn) / 256, 256>>>();

    dim3 gsc(Nn / 128, Nn / 128, Bn);
    scores_mma<<<gsc, 256, MMA_SMEM>>>(mask);

    dim3 gpv(Nn / 64, 1, Bn);
    pv_fused<<<gpv, 256, PV_SMEM>>>(mask, queries, out);
}

// round 11
// speedup vs baseline: 1.2052x; 1.0942x over previous
#include <cuda_runtime.h>
#include <cuda_bf16.h>
#include <cstdint>
#include <math.h>

#define Bn 8
#define Cn 256
#define Nn 4096

#define L2E 1.4426950408889634f
#define C2  72.134752f        // 50 * log2(e)

// ---------------------------------------------------------------------------
// Scratch
// ---------------------------------------------------------------------------
__device__ __nv_bfloat16 g_xqh[(size_t)Bn * Nn * Cn];  // queries^T hi [B,N,C]
__device__ __nv_bfloat16 g_xql[(size_t)Bn * Nn * Cn];
__device__ __nv_bfloat16 g_xkh[(size_t)Bn * Nn * Cn];  // keys^T hi [B,N,C]
__device__ __nv_bfloat16 g_xkl[(size_t)Bn * Nn * Cn];
__device__ __nv_bfloat16 g_wh[3 * Cn * Cn];            // Wq|Wk|Wv hi [O,C]
__device__ __nv_bfloat16 g_wl[3 * Cn * Cn];
__device__ __nv_bfloat16 g_qh[(size_t)Bn * Nn * Cn];   // q hi [B,N,C]
__device__ __nv_bfloat16 g_ql[(size_t)Bn * Nn * Cn];
__device__ __nv_bfloat16 g_kh[(size_t)Bn * Nn * Cn];   // k hi [B,N,C]
__device__ __nv_bfloat16 g_kl[(size_t)Bn * Nn * Cn];
__device__ __nv_bfloat16 g_vh[(size_t)Bn * Cn * Nn];   // v hi [B,C,N]
__device__ __nv_bfloat16 g_vl[(size_t)Bn * Cn * Nn];
__device__ __nv_bfloat16 g_Eh[(size_t)Bn * Nn * Nn];   // exp(s-50) hi [B,N,N]
__device__ __nv_bfloat16 g_El[(size_t)Bn * Nn * Nn];
__device__ float         g_Z [(size_t)Bn * Nn];        // row exp sums

// ---------------------------------------------------------------------------
// Helpers
// ---------------------------------------------------------------------------
__device__ __forceinline__ uint32_t smem_u32(const void* p) {
    uint32_t a;
    asm("{ .reg .u64 t; cvta.to.shared.u64 t, %1; cvt.u32.u64 %0, t; }"
        : "=r"(a) : "l"(p));
    return a;
}

#define SMEM_SWIZZLE_64B(off) ((off) ^ (((off) >> 3) & 0x30))

__device__ __forceinline__ void ldmx4(uint32_t* r, uint32_t a) {
    asm volatile("ldmatrix.sync.aligned.m8n8.x4.shared.b16 {%0,%1,%2,%3}, [%4];"
        : "=r"(r[0]), "=r"(r[1]), "=r"(r[2]), "=r"(r[3]) : "r"(a));
}

__device__ __forceinline__ void mma16816(float* d, const uint32_t* a,
                                         uint32_t b0, uint32_t b1) {
    asm volatile(
        "mma.sync.aligned.m16n8k16.row.col.f32.bf16.bf16.f32 "
        "{%0,%1,%2,%3}, {%4,%5,%6,%7}, {%8,%9}, {%0,%1,%2,%3};"
        : "+f"(d[0]), "+f"(d[1]), "+f"(d[2]), "+f"(d[3])
        : "r"(a[0]), "r"(a[1]), "r"(a[2]), "r"(a[3]), "r"(b0), "r"(b1));
}

__device__ __forceinline__ float ex2f(float x) {
    float y;
    asm("ex2.approx.f32 %0, %1;" : "=f"(y) : "f"(x));
    return y;
}

__device__ __forceinline__ uint32_t pack2(float a, float b, float& ra, float& rb) {
    __nv_bfloat16 ah = __float2bfloat16_rn(a);
    __nv_bfloat16 bh = __float2bfloat16_rn(b);
    ra = a - __bfloat162float(ah);
    rb = b - __bfloat162float(bh);
    __nv_bfloat162 t = __halves2bfloat162(ah, bh);
    return *reinterpret_cast<uint32_t*>(&t);
}

__device__ __forceinline__ uint32_t pack2lo(float a, float b) {
    __nv_bfloat162 t = __halves2bfloat162(__float2bfloat16_rn(a),
                                          __float2bfloat16_rn(b));
    return *reinterpret_cast<uint32_t*>(&t);
}

#define CP16(d, s) \
    asm volatile("cp.async.cg.shared.global [%0], [%1], 16;" :: "r"(d), "l"(s))
#define CP_COMMIT() asm volatile("cp.async.commit_group;" ::: "memory")
#define CP_WAIT1()  asm volatile("cp.async.wait_group 1;" ::: "memory")
#define CP_WAIT0()  asm volatile("cp.async.wait_group 0;" ::: "memory")

// ---------------------------------------------------------------------------
// Shared GEMM mainloop: 3 stages x 4 tiles (Ah,Al,Bh,Bl) x 8KB = 96KB
// ---------------------------------------------------------------------------
#define TILE_B   8192
#define STAGE_B  (4 * TILE_B)
#define NSTAGES  3
#define MMA_SMEM (NSTAGES * STAGE_B)

__device__ __forceinline__ void cp_tile(uint32_t sdst, const __nv_bfloat16* g,
                                        int rs, int tid) {
    #pragma unroll
    for (int t = 0; t < 2; t++) {
        int u = tid + t * 256;
        int row = u >> 2, q = u & 3;
        uint32_t d = sdst + SMEM_SWIZZLE_64B((uint32_t)(row * 64 + q * 16));
        CP16(d, g + (size_t)row * rs + q * 8);
    }
}

// acc[4][4][4] += A(128xK) @ B(128xK)^T, 2-way bf16 split (hh+hl+lh),
// product-major ordering. 8 warps: warp tile 64(i) x 32(j).
__device__ __forceinline__ void mma_mainloop(
    uint32_t sbase,
    const __nv_bfloat16* Ah, const __nv_bfloat16* Al,
    const __nv_bfloat16* Bh, const __nv_bfloat16* Bl,
    int rsA, int rsB, int nch,
    float acc[4][4][4], int tid, int wid, int lane)
{
    const int iBase = (wid >> 2) * 64;
    const int jBase = (wid & 3) * 32;
    const uint32_t lsw  = (uint32_t)(((lane >> 1) & 3) * 16);
    const uint32_t aoff = (uint32_t)((iBase + (lane & 15)) * 64 + (lane >> 4) * 16);
    const uint32_t boff = (uint32_t)((jBase + (lane & 15)) * 64 + (lane >> 4) * 16);

    #pragma unroll
    for (int p = 0; p < 2; p++) {
        uint32_t st = sbase + p * STAGE_B;
        int ko = p * 32;
        cp_tile(st + 0 * TILE_B, Ah + ko, rsA, tid);
        cp_tile(st + 1 * TILE_B, Al + ko, rsA, tid);
        cp_tile(st + 2 * TILE_B, Bh + ko, rsB, tid);
        cp_tile(st + 3 * TILE_B, Bl + ko, rsB, tid);
        CP_COMMIT();
    }

    int stage = 0;
    #pragma unroll 1
    for (int c = 0; c < nch; c++) {
        if (c + 1 < nch) CP_WAIT1(); else CP_WAIT0();
        __syncthreads();

        if (c + 2 < nch) {
            int ps = stage + 2; if (ps >= NSTAGES) ps -= NSTAGES;
            uint32_t st = sbase + ps * STAGE_B;
            int ko = (c + 2) * 32;
            cp_tile(st + 0 * TILE_B, Ah + ko, rsA, tid);
            cp_tile(st + 1 * TILE_B, Al + ko, rsA, tid);
            cp_tile(st + 2 * TILE_B, Bh + ko, rsB, tid);
            cp_tile(st + 3 * TILE_B, Bl + ko, rsB, tid);
            CP_COMMIT();
        }

        uint32_t tb = sbase + stage * STAGE_B;
        #pragma unroll
        for (int ks = 0; ks < 2; ks++) {
            uint32_t kb = (uint32_t)(ks * 32);
            uint32_t ah[4][4], al[4][4];
            #pragma unroll
            for (int it = 0; it < 4; it++) {
                uint32_t o = (aoff + it * 1024 + kb) ^ lsw;
                ldmx4(ah[it], tb + o);
                ldmx4(al[it], tb + TILE_B + o);
            }
            uint32_t bh[4][2], bl[4][2];
            #pragma unroll
            for (int jp = 0; jp < 2; jp++) {
                uint32_t o = (boff + jp * 1024 + kb) ^ lsw;
                uint32_t t4[4];
                ldmx4(t4, tb + 2 * TILE_B + o);
                bh[jp * 2][0]     = t4[0]; bh[jp * 2][1]     = t4[2];
                bh[jp * 2 + 1][0] = t4[1]; bh[jp * 2 + 1][1] = t4[3];
                ldmx4(t4, tb + 3 * TILE_B + o);
                bl[jp * 2][0]     = t4[0]; bl[jp * 2][1]     = t4[2];
                bl[jp * 2 + 1][0] = t4[1]; bl[jp * 2 + 1][1] = t4[3];
            }
            #pragma unroll
            for (int it = 0; it < 4; it++)
                #pragma unroll
                for (int nt = 0; nt < 4; nt++)
                    mma16816(acc[it][nt], ah[it], bh[nt][0], bh[nt][1]);
            #pragma unroll
            for (int it = 0; it < 4; it++)
                #pragma unroll
                for (int nt = 0; nt < 4; nt++)
                    mma16816(acc[it][nt], ah[it], bl[nt][0], bl[nt][1]);
            #pragma unroll
            for (int it = 0; it < 4; it++)
                #pragma unroll
                for (int nt = 0; nt < 4; nt++)
                    mma16816(acc[it][nt], al[it], bh[nt][0], bh[nt][1]);
        }
        if (++stage == NSTAGES) stage = 0;
    }
}

// ---------------------------------------------------------------------------
// Kernel A: transpose + bf16 hi/lo split.  x [B,C,N] fp32 -> out [B,N,C].
// ---------------------------------------------------------------------------
__global__ void __launch_bounds__(256)
conv_split(const float* __restrict__ x,
           __nv_bfloat16* __restrict__ oh,
           __nv_bfloat16* __restrict__ ol) {
    __shared__ float ts[32][33];
    const int b = blockIdx.z, c0 = blockIdx.y * 32, n0 = blockIdx.x * 32;
    const int r = threadIdx.x >> 5, col = threadIdx.x & 31;

    const float* xb = x + ((size_t)b * Cn + c0) * Nn + n0;
    #pragma unroll
    for (int p = 0; p < 4; p++)
        ts[r + p * 8][col] = xb[(size_t)(r + p * 8) * Nn + col];
    __syncthreads();

    __nv_bfloat16* dh = oh + ((size_t)b * Nn + n0) * Cn + c0;
    __nv_bfloat16* dl = ol + ((size_t)b * Nn + n0) * Cn + c0;
    #pragma unroll
    for (int p = 0; p < 4; p++) {
        int n = r + p * 8;
        float f = ts[col][n];
        __nv_bfloat16 h = __float2bfloat16_rn(f);
        dh[(size_t)n * Cn + col] = h;
        dl[(size_t)n * Cn + col] = __float2bfloat16_rn(f - __bfloat162float(h));
    }
}

// ---------------------------------------------------------------------------
// Kernel B: split W matrices (768 blocks) + zero Z (128 blocks).
// ---------------------------------------------------------------------------
__global__ void __launch_bounds__(256)
wsplit_zero(const float* __restrict__ Wq, const float* __restrict__ Wk,
            const float* __restrict__ Wv) {
    int bid = blockIdx.x;
    if (bid < 768) {
        int idx = bid * 256 + threadIdx.x;
        int which = idx >> 16, off = idx & 65535;
        const float* s = (which == 0) ? Wq : (which == 1) ? Wk : Wv;
        float f = s[off];
        __nv_bfloat16 h = __float2bfloat16_rn(f);
        g_wh[idx] = h;
        g_wl[idx] = __float2bfloat16_rn(f - __bfloat162float(h));
    } else {
        g_Z[(size_t)(bid - 768) * 256 + threadIdx.x] = 0.f;
    }
}

// ---------------------------------------------------------------------------
// Kernel C1: projection GEMM -> [N, C] layout (q, k).
// out[n,o] = sum_c xT[n,c] * W[o,c] + bias[o]
// ---------------------------------------------------------------------------
__global__ void __launch_bounds__(256, 2)
proj_nk(const __nv_bfloat16* __restrict__ xh, const __nv_bfloat16* __restrict__ xl,
        const __nv_bfloat16* __restrict__ wh, const __nv_bfloat16* __restrict__ wl,
        const float* __restrict__ bias,
        __nv_bfloat16* __restrict__ oh, __nv_bfloat16* __restrict__ ol) {
    extern __shared__ char smem[];
    uint32_t sbase = smem_u32(smem);
    const int tid = threadIdx.x;
    const int wid = tid >> 5, lane = tid & 31;

    const int b  = blockIdx.z;
    const int n0 = blockIdx.y * 128;
    const int o0 = blockIdx.x * 128;

    float acc[4][4][4] = {};
    mma_mainloop(sbase,
                 xh + ((size_t)b * Nn + n0) * Cn, xl + ((size_t)b * Nn + n0) * Cn,
                 wh + (size_t)o0 * Cn,            wl + (size_t)o0 * Cn,
                 Cn, Cn, Cn / 32, acc, tid, wid, lane);

    const int iBase = (wid >> 2) * 64;
    const int jBase = (wid & 3) * 32;
    const int g = lane >> 2, cp2 = (lane & 3) * 2;
    __nv_bfloat16* dh = oh + (size_t)b * Nn * Cn;
    __nv_bfloat16* dl = ol + (size_t)b * Nn * Cn;

    #pragma unroll
    for (int nt = 0; nt < 4; nt++) {
        int cc = o0 + jBase + nt * 8 + cp2;
        float b0 = bias[cc], b1 = bias[cc + 1];
        #pragma unroll
        for (int it = 0; it < 4; it++) {
            int r1 = n0 + iBase + it * 16 + g;
            float l0, l1;
            uint32_t h01 = pack2(acc[it][nt][0] + b0, acc[it][nt][1] + b1, l0, l1);
            *reinterpret_cast<uint32_t*>(&dh[(size_t)r1 * Cn + cc]) = h01;
            *reinterpret_cast<uint32_t*>(&dl[(size_t)r1 * Cn + cc]) = pack2lo(l0, l1);
            uint32_t h23 = pack2(acc[it][nt][2] + b0, acc[it][nt][3] + b1, l0, l1);
            *reinterpret_cast<uint32_t*>(&dh[(size_t)(r1 + 8) * Cn + cc]) = h23;
            *reinterpret_cast<uint32_t*>(&dl[(size_t)(r1 + 8) * Cn + cc]) = pack2lo(l0, l1);
        }
    }
}

// ---------------------------------------------------------------------------
// Kernel C2: projection GEMM -> [C, N] layout (v).
// out[o,n] = sum_c W[o,c] * xT[n,c] + bias[o]
// ---------------------------------------------------------------------------
__global__ void __launch_bounds__(256, 2)
proj_cn(const __nv_bfloat16* __restrict__ wh, const __nv_bfloat16* __restrict__ wl,
        const __nv_bfloat16* __restrict__ xh, const __nv_bfloat16* __restrict__ xl,
        const float* __restrict__ bias,
        __nv_bfloat16* __restrict__ oh, __nv_bfloat16* __restrict__ ol) {
    extern __shared__ char smem[];
    uint32_t sbase = smem_u32(smem);
    const int tid = threadIdx.x;
    const int wid = tid >> 5, lane = tid & 31;

    const int b  = blockIdx.z;
    const int o0 = blockIdx.y * 128;
    const int n0 = blockIdx.x * 128;

    float acc[4][4][4] = {};
    mma_mainloop(sbase,
                 wh + (size_t)o0 * Cn,            wl + (size_t)o0 * Cn,
                 xh + ((size_t)b * Nn + n0) * Cn, xl + ((size_t)b * Nn + n0) * Cn,
                 Cn, Cn, Cn / 32, acc, tid, wid, lane);

    const int iBase = (wid >> 2) * 64;
    const int jBase = (wid & 3) * 32;
    const int g = lane >> 2, cp2 = (lane & 3) * 2;
    __nv_bfloat16* dh = oh + (size_t)b * Cn * Nn;
    __nv_bfloat16* dl = ol + (size_t)b * Cn * Nn;

    #pragma unroll
    for (int it = 0; it < 4; it++) {
        int r1 = o0 + iBase + it * 16 + g;
        float br1 = bias[r1], br2 = bias[r1 + 8];
        #pragma unroll
        for (int nt = 0; nt < 4; nt++) {
            int cc = n0 + jBase + nt * 8 + cp2;
            float l0, l1;
            uint32_t h01 = pack2(acc[it][nt][0] + br1, acc[it][nt][1] + br1, l0, l1);
            *reinterpret_cast<uint32_t*>(&dh[(size_t)r1 * Nn + cc]) = h01;
            *reinterpret_cast<uint32_t*>(&dl[(size_t)r1 * Nn + cc]) = pack2lo(l0, l1);
            uint32_t h23 = pack2(acc[it][nt][2] + br2, acc[it][nt][3] + br2, l0, l1);
            *reinterpret_cast<uint32_t*>(&dh[(size_t)(r1 + 8) * Nn + cc]) = h23;
            *reinterpret_cast<uint32_t*>(&dl[(size_t)(r1 + 8) * Nn + cc]) = pack2lo(l0, l1);
        }
    }
}

// ---------------------------------------------------------------------------
// Kernel D: scores via HMMA; epilogue stores E = exp(s-50) bf16 hi/lo + Z sums.
// ---------------------------------------------------------------------------
__global__ void __launch_bounds__(256, 2)
scores_mma(const float* __restrict__ mask) {
    extern __shared__ char smem[];
    uint32_t sbase = smem_u32(smem);
    const int tid = threadIdx.x;
    const int wid = tid >> 5, lane = tid & 31;

    const int b  = blockIdx.z;
    const int i0 = blockIdx.y * 128;
    const int j0 = blockIdx.x * 128;

    float acc[4][4][4] = {};
    mma_mainloop(sbase,
                 g_qh + ((size_t)b * Nn + i0) * Cn, g_ql + ((size_t)b * Nn + i0) * Cn,
                 g_kh + ((size_t)b * Nn + j0) * Cn, g_kl + ((size_t)b * Nn + j0) * Cn,
                 Cn, Cn, Cn / 32, acc, tid, wid, lane);

    const int iBase = (wid >> 2) * 64;
    const int jBase = (wid & 3) * 32;
    const int g = lane >> 2, cp2 = (lane & 3) * 2;
    const float* mb = mask + (size_t)b * Nn;
    __nv_bfloat16* Ehb = g_Eh + (size_t)b * Nn * Nn;
    __nv_bfloat16* Elb = g_El + (size_t)b * Nn * Nn;
    float* Zb = g_Z + (size_t)b * Nn;

    #pragma unroll
    for (int it = 0; it < 4; it++) {
        int r1 = i0 + iBase + it * 16 + g;
        float m1 = mb[r1], m2 = mb[r1 + 8];
        float z1 = 0.f, z2 = 0.f;
        #pragma unroll
        for (int nt = 0; nt < 4; nt++) {
            int cc = j0 + jBase + nt * 8 + cp2;
            float e0 = ex2f(fmaf(acc[it][nt][0] * m1, L2E, -C2));
            float e1 = ex2f(fmaf(acc[it][nt][1] * m1, L2E, -C2));
            float e2 = ex2f(fmaf(acc[it][nt][2] * m2, L2E, -C2));
            float e3 = ex2f(fmaf(acc[it][nt][3] * m2, L2E, -C2));
            z1 += e0 + e1;
            z2 += e2 + e3;
            float l0, l1;
            uint32_t h01 = pack2(e0, e1, l0, l1);
            *reinterpret_cast<uint32_t*>(&Ehb[(size_t)r1 * Nn + cc]) = h01;
            *reinterpret_cast<uint32_t*>(&Elb[(size_t)r1 * Nn + cc]) = pack2lo(l0, l1);
            uint32_t h23 = pack2(e2, e3, l0, l1);
            *reinterpret_cast<uint32_t*>(&Ehb[(size_t)(r1 + 8) * Nn + cc]) = h23;
            *reinterpret_cast<uint32_t*>(&Elb[(size_t)(r1 + 8) * Nn + cc]) = pack2lo(l0, l1);
        }
        z1 += __shfl_xor_sync(0xffffffffu, z1, 1);
        z1 += __shfl_xor_sync(0xffffffffu, z1, 2);
        z2 += __shfl_xor_sync(0xffffffffu, z2, 1);
        z2 += __shfl_xor_sync(0xffffffffu, z2, 2);
        if ((lane & 3) == 0) {
            atomicAdd(&Zb[r1], z1);
            atomicAdd(&Zb[r1 + 8], z2);
        }
    }
}

// ---------------------------------------------------------------------------
// Kernel E: PV GEMM on unnormalized E + normalize/blend epilogue.
// O_raw[c,q] = sum_j V[c,j]*E[q,j];  out = queries*m + (1-m)*O_raw/Z[q]
// ---------------------------------------------------------------------------
__global__ void __launch_bounds__(256, 2)
pv_mma(const float* __restrict__ mask,
       const float* __restrict__ queries,
       float* __restrict__ out) {
    extern __shared__ char smem[];
    uint32_t sbase = smem_u32(smem);
    const int tid = threadIdx.x;
    const int wid = tid >> 5, lane = tid & 31;

    const int b  = blockIdx.z;
    const int c0 = blockIdx.y * 128;
    const int q0 = blockIdx.x * 128;

    float acc[4][4][4] = {};
    mma_mainloop(sbase,
                 g_vh + ((size_t)b * Cn + c0) * Nn, g_vl + ((size_t)b * Cn + c0) * Nn,
                 g_Eh + ((size_t)b * Nn + q0) * Nn, g_El + ((size_t)b * Nn + q0) * Nn,
                 Nn, Nn, Nn / 32, acc, tid, wid, lane);

    const int iBase = (wid >> 2) * 64;
    const int jBase = (wid & 3) * 32;
    const int g = lane >> 2, cp2 = (lane & 3) * 2;
    const float* mb = mask + (size_t)b * Nn;
    const float* Zb = g_Z + (size_t)b * Nn;

    int   qc[4];
    float m0[4], m1[4], iz0[4], iz1[4];
    #pragma unroll
    for (int nt = 0; nt < 4; nt++) {
        qc[nt] = q0 + jBase + nt * 8 + cp2;
        m0[nt] = mb[qc[nt]];
        m1[nt] = mb[qc[nt] + 1];
        iz0[nt] = __fdividef(1.f, Zb[qc[nt]]);
        iz1[nt] = __fdividef(1.f, Zb[qc[nt] + 1]);
    }

    #pragma unroll
    for (int it = 0; it < 4; it++) {
        int cr = c0 + iBase + it * 16 + g;
        #pragma unroll
        for (int nt = 0; nt < 4; nt++) {
            size_t gi1 = ((size_t)b * Cn + cr) * Nn + qc[nt];
            size_t gi2 = gi1 + (size_t)8 * Nn;
            float2 qa = *reinterpret_cast<const float2*>(&queries[gi1]);
            float2 qb = *reinterpret_cast<const float2*>(&queries[gi2]);
            float2 o1, o2;
            o1.x = qa.x * m0[nt] + (1.f - m0[nt]) * acc[it][nt][0] * iz0[nt];
            o1.y = qa.y * m1[nt] + (1.f - m1[nt]) * acc[it][nt][1] * iz1[nt];
            o2.x = qb.x * m0[nt] + (1.f - m0[nt]) * acc[it][nt][2] * iz0[nt];
            o2.y = qb.y * m1[nt] + (1.f - m1[nt]) * acc[it][nt][3] * iz1[nt];
            *reinterpret_cast<float2*>(&out[gi1]) = o1;
            *reinterpret_cast<float2*>(&out[gi2]) = o2;
        }
    }
}

// ---------------------------------------------------------------------------
// Launch
// ---------------------------------------------------------------------------
extern "C" void kernel_launch(void* const* d_in, const int* in_sizes, int n_in,
                              void* d_out, int out_size) {
    const float* queries = (const float*)d_in[0];
    const float* keys    = (const float*)d_in[1];
    const float* mask    = (const float*)d_in[2];
    const float* Wq      = (const float*)d_in[3];
    const float* bq      = (const float*)d_in[4];
    const float* Wk      = (const float*)d_in[5];
    const float* bk      = (const float*)d_in[6];
    const float* Wv      = (const float*)d_in[7];
    const float* bv      = (const float*)d_in[8];
    float* out = (float*)d_out;

    cudaFuncSetAttribute(proj_nk,    cudaFuncAttributeMaxDynamicSharedMemorySize, MMA_SMEM);
    cudaFuncSetAttribute(proj_cn,    cudaFuncAttributeMaxDynamicSharedMemorySize, MMA_SMEM);
    cudaFuncSetAttribute(scores_mma, cudaFuncAttributeMaxDynamicSharedMemorySize, MMA_SMEM);
    cudaFuncSetAttribute(pv_mma,     cudaFuncAttributeMaxDynamicSharedMemorySize, MMA_SMEM);

    __nv_bfloat16 *xqh, *xql, *xkh, *xkl, *wh, *wl, *qh, *ql, *kh, *kl, *vh, *vl;
    cudaGetSymbolAddress((void**)&xqh, g_xqh);
    cudaGetSymbolAddress((void**)&xql, g_xql);
    cudaGetSymbolAddress((void**)&xkh, g_xkh);
    cudaGetSymbolAddress((void**)&xkl, g_xkl);
    cudaGetSymbolAddress((void**)&wh,  g_wh);
    cudaGetSymbolAddress((void**)&wl,  g_wl);
    cudaGetSymbolAddress((void**)&qh,  g_qh);
    cudaGetSymbolAddress((void**)&ql,  g_ql);
    cudaGetSymbolAddress((void**)&kh,  g_kh);
    cudaGetSymbolAddress((void**)&kl,  g_kl);
    cudaGetSymbolAddress((void**)&vh,  g_vh);
    cudaGetSymbolAddress((void**)&vl,  g_vl);

    // Input transpose + split
    dim3 gcv(Nn / 32, Cn / 32, Bn);
    conv_split<<<gcv, 256>>>(queries, xqh, xql);
    conv_split<<<gcv, 256>>>(keys,    xkh, xkl);
    wsplit_zero<<<896, 256>>>(Wq, Wk, Wv);

    // Projections via HMMA
    dim3 gnk(Cn / 128, Nn / 128, Bn);
    proj_nk<<<gnk, 256, MMA_SMEM>>>(xqh, xql, wh,              wl,              bq, qh, ql);
    proj_nk<<<gnk, 256, MMA_SMEM>>>(xkh, xkl, wh + Cn * Cn,    wl + Cn * Cn,    bk, kh, kl);
    dim3 gcn(Nn / 128, Cn / 128, Bn);
    proj_cn<<<gcn, 256, MMA_SMEM>>>(wh + 2 * Cn * Cn, wl + 2 * Cn * Cn, xkh, xkl, bv, vh, vl);

    // Scores -> E (unnormalized exp) + Z
    dim3 gsc(Nn / 128, Nn / 128, Bn);
    scores_mma<<<gsc, 256, MMA_SMEM>>>(mask);

    // PV + normalize + blend
    dim3 gpv(Nn / 128, Cn / 128, Bn);
    pv_mma<<<gpv, 256, MMA_SMEM>>>(mask, queries, out);
}